// round 7
// baseline (speedup 1.0000x reference)
#include <cuda_runtime.h>
#include <math.h>

// RotorQuantMSE — R7: barrier-free hot kernel via precomputed norms.
// Kernel A: warp-per-row L2 norms (dense LDG.128) -> g_norm; block 0 also
//           bakes the 256 rotor-sandwich 3x3 matrices -> g_mat.
// Kernel B: thread owns 12 consecutive floats (4 whole groups). No smem, no
//           shuffles, no barriers, no selects — pure independent streaming.

#define D 768
#define GMAX 256
#define NMAX 8192

__device__ __align__(16) float g_mat[GMAX * 12];   // [G][12] row-major + pad
__device__ float g_norm[NMAX];

__device__ __forceinline__ void rotor_apply(
    float r0, float b1, float b2, float b3,
    float v1, float v2, float v3,
    float& o1, float& o2, float& o3)
{
    float t1 = fmaf(r0, v1, fmaf(b1, v2,  b2 * v3));
    float t2 = fmaf(r0, v2, fmaf(-b1, v1, b3 * v3));
    float t3 = fmaf(r0, v3, fmaf(-b2, v1, -b3 * v2));
    float t7 = fmaf(b1, v3, fmaf(-b2, v2,  b3 * v1));
    o1 = fmaf(r0, t1, fmaf( b1, t2, fmaf( b2, t3,  b3 * t7)));
    o2 = fmaf(r0, t2, fmaf(-b1, t1, fmaf( b3, t3, -b2 * t7)));
    o3 = fmaf(r0, t3, fmaf(-b2, t1, fmaf(-b3, t2,  b1 * t7)));
}

// Kernel A: norms (warp per row) + matrix table (block 0)
__global__ void __launch_bounds__(256)
prep_kernel(const float* __restrict__ x,
            const float* __restrict__ rotors,
            float* __restrict__ norms_out,
            int N, int G)
{
    const int w = threadIdx.x >> 5;
    const int l = threadIdx.x & 31;
    const int row = blockIdx.x * 8 + w;

    if (row < N) {
        const float4* px = reinterpret_cast<const float4*>(x + (size_t)row * D);
        float sq = 0.0f;
        #pragma unroll
        for (int j = 0; j < 6; j++) {
            float4 a = __ldg(px + l + 32 * j);
            sq = fmaf(a.x, a.x, fmaf(a.y, a.y, fmaf(a.z, a.z, fmaf(a.w, a.w, sq))));
        }
        #pragma unroll
        for (int o = 16; o; o >>= 1) sq += __shfl_xor_sync(0xffffffffu, sq, o);
        if (l == 0) {
            float nrm = fmaxf(sqrtf(sq), 1e-8f);
            g_norm[row] = nrm;
            if (norms_out) norms_out[row] = nrm;
        }
    }

    if (blockIdx.x == 0) {
        int g = threadIdx.x;
        if (g < G) {
            const float* rp = rotors + (size_t)g * 8;
            float r0 = rp[0], b1 = rp[4], b2 = rp[5], b3 = rp[6];
            float M[12];
            rotor_apply(r0, b1, b2, b3, 1.f, 0.f, 0.f, M[0], M[3], M[6]);
            rotor_apply(r0, b1, b2, b3, 0.f, 1.f, 0.f, M[1], M[4], M[7]);
            rotor_apply(r0, b1, b2, b3, 0.f, 0.f, 1.f, M[2], M[5], M[8]);
            M[9] = M[10] = M[11] = 0.f;
            float4* dst = reinterpret_cast<float4*>(g_mat + g * 12);
            dst[0] = make_float4(M[0], M[1],  M[2],  M[3]);
            dst[1] = make_float4(M[4], M[5],  M[6],  M[7]);
            dst[2] = make_float4(M[8], M[9], M[10], M[11]);
        }
    }
}

// Kernel B: the hot streaming kernel. 64 threads per row, 4 rows per block.
__global__ void __launch_bounds__(256)
rotor_quant_kernel(const float* __restrict__ x,
                   float* __restrict__ xhat,
                   float* __restrict__ idx_out)
{
    const int tid = threadIdx.x;
    const int s   = tid >> 6;            // row slot 0..3
    const int t   = tid & 63;            // owns floats 12t..12t+11 (groups 4t..4t+3)
    const int row = blockIdx.x * 4 + s;

    const float nrm = g_norm[row];
    const float inv = 1.0f / nrm;
    const float step = 2.0f / 15.0f;

    // dense-per-thread strided loads: 3 consecutive float4s
    const float4* px = reinterpret_cast<const float4*>(x + (size_t)row * D + 12 * t);
    float4 a0 = __ldg(px + 0), a1 = __ldg(px + 1), a2 = __ldg(px + 2);
    const float v[12] = { a0.x, a0.y, a0.z, a0.w,
                          a1.x, a1.y, a1.z, a1.w,
                          a2.x, a2.y, a2.z, a2.w };

    const float4* mp = reinterpret_cast<const float4*>(g_mat + (size_t)(4 * t) * 12);

    float h[12], fk[12];
    #pragma unroll
    for (int g = 0; g < 4; g++) {
        float4 m0 = __ldg(mp + 3 * g + 0);
        float4 m1 = __ldg(mp + 3 * g + 1);
        float4 m2 = __ldg(mp + 3 * g + 2);
        const float M[9] = { m0.x, m0.y, m0.z, m0.w, m1.x, m1.y, m1.z, m1.w, m2.x };
        const float a = v[3*g], b = v[3*g + 1], c = v[3*g + 2];

        // forward rotation of normalized vector
        float y0 = fmaf(M[0], a, fmaf(M[1], b, M[2] * c)) * inv;
        float y1 = fmaf(M[3], a, fmaf(M[4], b, M[5] * c)) * inv;
        float y2 = fmaf(M[6], a, fmaf(M[7], b, M[8] * c)) * inv;

        // argmin |y - c_k| over linspace(-1,1,16), ties -> lower index
        int k0 = max(0, min(15, (int)ceilf(fmaf(y0 + 1.0f, 7.5f, -0.5f))));
        int k1 = max(0, min(15, (int)ceilf(fmaf(y1 + 1.0f, 7.5f, -0.5f))));
        int k2 = max(0, min(15, (int)ceilf(fmaf(y2 + 1.0f, 7.5f, -0.5f))));
        fk[3*g] = (float)k0; fk[3*g+1] = (float)k1; fk[3*g+2] = (float)k2;

        float q0 = fmaf((float)k0, step, -1.0f);
        float q1 = fmaf((float)k1, step, -1.0f);
        float q2 = fmaf((float)k2, step, -1.0f);

        // inverse rotation = M^T, rescale
        h[3*g]   = fmaf(M[0], q0, fmaf(M[3], q1, M[6] * q2)) * nrm;
        h[3*g+1] = fmaf(M[1], q0, fmaf(M[4], q1, M[7] * q2)) * nrm;
        h[3*g+2] = fmaf(M[2], q0, fmaf(M[5], q1, M[8] * q2)) * nrm;
    }

    float4* ph = reinterpret_cast<float4*>(xhat + (size_t)row * D + 12 * t);
    ph[0] = make_float4(h[0], h[1], h[2],  h[3]);
    ph[1] = make_float4(h[4], h[5], h[6],  h[7]);
    ph[2] = make_float4(h[8], h[9], h[10], h[11]);
    if (idx_out) {
        float4* pi = reinterpret_cast<float4*>(idx_out + (size_t)row * D + 12 * t);
        pi[0] = make_float4(fk[0], fk[1], fk[2],  fk[3]);
        pi[1] = make_float4(fk[4], fk[5], fk[6],  fk[7]);
        pi[2] = make_float4(fk[8], fk[9], fk[10], fk[11]);
    }
}

extern "C" void kernel_launch(void* const* d_in, const int* in_sizes, int n_in,
                              void* d_out, int out_size)
{
    const float* x      = (const float*)d_in[0];   // [N, d]
    const float* rotors = (const float*)d_in[2];   // [G, 8]

    const int G = in_sizes[2] / 8;        // 256
    const int d = 3 * G;                  // 768
    const int N = in_sizes[0] / d;        // 8192

    float* out   = (float*)d_out;
    float* xhat  = out;
    float* idxp  = nullptr;
    float* normp = nullptr;
    const long nd = (long)N * d;
    if ((long)out_size >= 2 * nd)     idxp  = out + nd;
    if ((long)out_size >= 2 * nd + N) normp = out + 2 * nd;

    prep_kernel<<<(N + 7) / 8, 256>>>(x, rotors, normp, N, G);
    rotor_quant_kernel<<<N / 4, 256>>>(x, xhat, idxp);
}

// round 8
// speedup vs baseline: 1.2352x; 1.2352x over previous
#include <cuda_runtime.h>
#include <math.h>

// RotorQuantMSE — R8: R3's dense-float4 + shuffle-exchange hot path (measured
// best), made barrier-free by precomputing row norms in a prep kernel.
// Hot kernel: persistent, 192 thr = 1 row, matrices in registers, no smem,
// no barriers, no reductions. Prep: warp-per-row dense norm.

#define D 768
#define NMAX 8192
#define NBLK 1184   // 148 SMs * 8

__device__ float g_norm[NMAX];

__device__ __forceinline__ void rotor_apply(
    float r0, float b1, float b2, float b3,
    float v1, float v2, float v3,
    float& o1, float& o2, float& o3)
{
    float t1 = fmaf(r0, v1, fmaf(b1, v2,  b2 * v3));
    float t2 = fmaf(r0, v2, fmaf(-b1, v1, b3 * v3));
    float t3 = fmaf(r0, v3, fmaf(-b2, v1, -b3 * v2));
    float t7 = fmaf(b1, v3, fmaf(-b2, v2,  b3 * v1));
    o1 = fmaf(r0, t1, fmaf( b1, t2, fmaf( b2, t3,  b3 * t7)));
    o2 = fmaf(r0, t2, fmaf(-b1, t1, fmaf( b3, t3, -b2 * t7)));
    o3 = fmaf(r0, t3, fmaf(-b2, t1, fmaf(-b3, t2,  b1 * t7)));
}

__device__ __forceinline__ void build_mat(const float* __restrict__ rp, float M[9])
{
    float r0 = __ldg(rp + 0);
    float4 bv = __ldg(reinterpret_cast<const float4*>(rp + 4));
    float b1 = bv.x, b2 = bv.y, b3 = bv.z;
    rotor_apply(r0, b1, b2, b3, 1.f, 0.f, 0.f, M[0], M[3], M[6]);
    rotor_apply(r0, b1, b2, b3, 0.f, 1.f, 0.f, M[1], M[4], M[7]);
    rotor_apply(r0, b1, b2, b3, 0.f, 0.f, 1.f, M[2], M[5], M[8]);
}

// prep: warp per row, dense LDG.128, writes g_norm (+ optional norms output)
__global__ void __launch_bounds__(256)
prep_kernel(const float* __restrict__ x, float* __restrict__ norms_out, int N)
{
    const int w = threadIdx.x >> 5;
    const int l = threadIdx.x & 31;
    const int row = blockIdx.x * 8 + w;
    if (row >= N) return;
    const float4* px = reinterpret_cast<const float4*>(x + (size_t)row * D);
    float sq = 0.0f;
    #pragma unroll
    for (int j = 0; j < 6; j++) {
        float4 a = __ldg(px + l + 32 * j);
        sq = fmaf(a.x, a.x, fmaf(a.y, a.y, fmaf(a.z, a.z, fmaf(a.w, a.w, sq))));
    }
    #pragma unroll
    for (int o = 16; o; o >>= 1) sq += __shfl_xor_sync(0xffffffffu, sq, o);
    if (l == 0) {
        float nrm = fmaxf(sqrtf(sq), 1e-8f);
        g_norm[row] = nrm;
        if (norms_out) norms_out[row] = nrm;
    }
}

__device__ __forceinline__ int quant(float y)
{
    // argmin |y - c_k| over linspace(-1,1,16), ties -> lower index
    int k = (int)ceilf(fmaf(y + 1.0f, 7.5f, -0.5f));
    return max(0, min(15, k));
}

__global__ void __launch_bounds__(192)
rotor_quant_kernel(const float* __restrict__ x,
                   const float* __restrict__ rotors,
                   float* __restrict__ xhat,
                   float* __restrict__ idx_out,
                   int N)
{
    const int w = threadIdx.x >> 5;      // warp 0..5
    const int l = threadIdx.x & 31;
    const int p0 = 128 * w + 4 * l;      // first float position in row
    const int m  = p0 % 3;               // alignment within group
    const int gA = p0 / 3;               // first overlapped group (gB = gA+1)
    const int f4 = 32 * w + l;           // float4 index within row

    float MA[9], MB[9];
    build_mat(rotors + (size_t)gA * 8, MA);
    build_mat(rotors + (size_t)(gA + 1) * 8, MB);

    const bool needPrev = (l == 0)  && ((128 * w) % 3 != 0);
    const bool needNext = (l == 31) && ((128 * (w + 1)) % 3 != 0);
    const float step = 2.0f / 15.0f;

    // prologue loads for first row
    int row = blockIdx.x;
    float4 a = make_float4(0, 0, 0, 0);
    float2 pv = make_float2(0, 0), nx = make_float2(0, 0);
    float nrm = 1.0f;
    if (row < N) {
        const float* xr = x + (size_t)row * D;
        a = __ldg(reinterpret_cast<const float4*>(xr) + f4);
        if (needPrev) pv = __ldg(reinterpret_cast<const float2*>(xr + 128 * w - 2));
        if (needNext) nx = __ldg(reinterpret_cast<const float2*>(xr + 128 * (w + 1)));
        nrm = g_norm[row];
    }

    for (; row < N; row += NBLK) {
        // prefetch next row (no barriers anywhere in this loop)
        const int nrow = row + NBLK;
        float4 a2 = make_float4(0, 0, 0, 0);
        float2 pv2 = make_float2(0, 0), nx2 = make_float2(0, 0);
        float nrm2 = 1.0f;
        if (nrow < N) {
            const float* xr2 = x + (size_t)nrow * D;
            a2 = __ldg(reinterpret_cast<const float4*>(xr2) + f4);
            if (needPrev) pv2 = __ldg(reinterpret_cast<const float2*>(xr2 + 128 * w - 2));
            if (needNext) nx2 = __ldg(reinterpret_cast<const float2*>(xr2 + 128 * (w + 1)));
            nrm2 = g_norm[nrow];
        }

        const float inv = 1.0f / nrm;

        // neighbor exchange: e[k] = row float at p0-2+k
        float e0 = __shfl_up_sync(0xffffffffu, a.z, 1);
        float e1 = __shfl_up_sync(0xffffffffu, a.w, 1);
        float e6 = __shfl_down_sync(0xffffffffu, a.x, 1);
        float e7 = __shfl_down_sync(0xffffffffu, a.y, 1);
        if (l == 0)  { e0 = pv.x; e1 = pv.y; }
        if (l == 31) { e6 = nx.x; e7 = nx.y; }
        const float e2 = a.x, e3 = a.y, e4 = a.z, e5 = a.w;

        float vA0 = (m == 0) ? e2 : (m == 1) ? e1 : e0;
        float vA1 = (m == 0) ? e3 : (m == 1) ? e2 : e1;
        float vA2 = (m == 0) ? e4 : (m == 1) ? e3 : e2;
        float vB0 = (m == 0) ? e5 : (m == 1) ? e4 : e3;
        float vB1 = (m == 0) ? e6 : (m == 1) ? e5 : e4;
        float vB2 = (m == 0) ? e7 : (m == 1) ? e6 : e5;

        float yA0 = fmaf(MA[0], vA0, fmaf(MA[1], vA1, MA[2] * vA2)) * inv;
        float yA1 = fmaf(MA[3], vA0, fmaf(MA[4], vA1, MA[5] * vA2)) * inv;
        float yA2 = fmaf(MA[6], vA0, fmaf(MA[7], vA1, MA[8] * vA2)) * inv;
        float yB0 = fmaf(MB[0], vB0, fmaf(MB[1], vB1, MB[2] * vB2)) * inv;
        float yB1 = fmaf(MB[3], vB0, fmaf(MB[4], vB1, MB[5] * vB2)) * inv;
        float yB2 = fmaf(MB[6], vB0, fmaf(MB[7], vB1, MB[8] * vB2)) * inv;

        int kA0 = quant(yA0), kA1 = quant(yA1), kA2 = quant(yA2);
        int kB0 = quant(yB0), kB1 = quant(yB1), kB2 = quant(yB2);
        float qA0 = fmaf((float)kA0, step, -1.0f);
        float qA1 = fmaf((float)kA1, step, -1.0f);
        float qA2 = fmaf((float)kA2, step, -1.0f);
        float qB0 = fmaf((float)kB0, step, -1.0f);
        float qB1 = fmaf((float)kB1, step, -1.0f);
        float qB2 = fmaf((float)kB2, step, -1.0f);

        float hA0 = fmaf(MA[0], qA0, fmaf(MA[3], qA1, MA[6] * qA2)) * nrm;
        float hA1 = fmaf(MA[1], qA0, fmaf(MA[4], qA1, MA[7] * qA2)) * nrm;
        float hA2 = fmaf(MA[2], qA0, fmaf(MA[5], qA1, MA[8] * qA2)) * nrm;
        float hB0 = fmaf(MB[0], qB0, fmaf(MB[3], qB1, MB[6] * qB2)) * nrm;
        float hB1 = fmaf(MB[1], qB0, fmaf(MB[4], qB1, MB[7] * qB2)) * nrm;
        float hB2 = fmaf(MB[2], qB0, fmaf(MB[5], qB1, MB[8] * qB2)) * nrm;

        float4 oh, oi;
        oh.x = (m == 0) ? hA0 : (m == 1) ? hA1 : hA2;
        oh.y = (m == 0) ? hA1 : (m == 1) ? hA2 : hB0;
        oh.z = (m == 0) ? hA2 : (m == 1) ? hB0 : hB1;
        oh.w = (m == 0) ? hB0 : (m == 1) ? hB1 : hB2;
        oi.x = (float)((m == 0) ? kA0 : (m == 1) ? kA1 : kA2);
        oi.y = (float)((m == 0) ? kA1 : (m == 1) ? kA2 : kB0);
        oi.z = (float)((m == 0) ? kA2 : (m == 1) ? kB0 : kB1);
        oi.w = (float)((m == 0) ? kB0 : (m == 1) ? kB1 : kB2);

        reinterpret_cast<float4*>(xhat + (size_t)row * D)[f4] = oh;
        if (idx_out)
            reinterpret_cast<float4*>(idx_out + (size_t)row * D)[f4] = oi;

        a = a2; pv = pv2; nx = nx2; nrm = nrm2;
    }
}

extern "C" void kernel_launch(void* const* d_in, const int* in_sizes, int n_in,
                              void* d_out, int out_size)
{
    const float* x      = (const float*)d_in[0];   // [N, d]
    const float* rotors = (const float*)d_in[2];   // [G, 8]

    const int G = in_sizes[2] / 8;        // 256
    const int d = 3 * G;                  // 768
    const int N = in_sizes[0] / d;        // 8192

    float* out   = (float*)d_out;
    float* xhat  = out;
    float* idxp  = nullptr;
    float* normp = nullptr;
    const long nd = (long)N * d;
    if ((long)out_size >= 2 * nd)     idxp  = out + nd;
    if ((long)out_size >= 2 * nd + N) normp = out + 2 * nd;

    prep_kernel<<<(N + 7) / 8, 256>>>(x, normp, N);
    rotor_quant_kernel<<<NBLK, 192>>>(x, rotors, xhat, idxp, N);
}